// round 1
// baseline (speedup 1.0000x reference)
#include <cuda_runtime.h>

// Problem constants (fixed by the reference):
//   input : (32, 1, 1024, 1024) float32
//   x_A, y_A, x_B, y_B, ordinal : (32, 100000) int32
//   output: scalar float32 = mean loss over 3.2M points
#define BB    32
#define HH    1024
#define WW    1024
#define NPTS  100000
#define TOTAL (BB * NPTS)   // 3,200,000

__device__ double g_acc;

__global__ void zero_acc_kernel() {
    g_acc = 0.0;
}

__global__ __launch_bounds__(256) void loss_kernel(
    const float* __restrict__ depth,
    const int*   __restrict__ xA,
    const int*   __restrict__ yA,
    const int*   __restrict__ xB,
    const int*   __restrict__ yB,
    const int*   __restrict__ ordv)
{
    int i = blockIdx.x * blockDim.x + threadIdx.x;
    float l = 0.0f;
    if (i < TOTAL) {
        int b = i / NPTS;
        const float* img = depth + (size_t)b * (HH * WW);

        int ax = xA[i], ay = yA[i];
        int bx = xB[i], by = yB[i];
        int o  = ordv[i];

        float zA = __ldg(&img[ay * WW + ax]);
        float zB = __ldg(&img[by * WW + bx]);
        float diff = zA - zB;

        if (o == 1) {
            // gt = 0, mask = 0 -> squared loss
            l = diff * diff;
        } else {
            // gt = +-1, mask = 1 -> softplus(-gt * diff), numerically stable
            float gt = (float)(o - 1);
            float x  = -gt * diff;
            l = fmaxf(x, 0.0f) + log1pf(expf(-fabsf(x)));
        }
    }

    // Warp reduction
    #pragma unroll
    for (int off = 16; off > 0; off >>= 1)
        l += __shfl_down_sync(0xffffffffu, l, off);

    __shared__ float warpsums[8];
    int lane = threadIdx.x & 31;
    int wid  = threadIdx.x >> 5;
    if (lane == 0) warpsums[wid] = l;
    __syncthreads();

    if (wid == 0) {
        float s = (lane < 8) ? warpsums[lane] : 0.0f;
        #pragma unroll
        for (int off = 4; off > 0; off >>= 1)
            s += __shfl_down_sync(0xffffffffu, s, off);
        if (lane == 0)
            atomicAdd(&g_acc, (double)s);
    }
}

__global__ void finalize_kernel(float* out) {
    *out = (float)(g_acc / (double)TOTAL);
}

extern "C" void kernel_launch(void* const* d_in, const int* in_sizes, int n_in,
                              void* d_out, int out_size)
{
    const float* depth = (const float*)d_in[0];
    const int*   xA    = (const int*)d_in[1];
    const int*   yA    = (const int*)d_in[2];
    const int*   xB    = (const int*)d_in[3];
    const int*   yB    = (const int*)d_in[4];
    const int*   ordv  = (const int*)d_in[5];
    float*       out   = (float*)d_out;

    zero_acc_kernel<<<1, 1>>>();

    const int threads = 256;
    const int blocks  = (TOTAL + threads - 1) / threads;  // 12500
    loss_kernel<<<blocks, threads>>>(depth, xA, yA, xB, yB, ordv);

    finalize_kernel<<<1, 1>>>(out);
}

// round 2
// speedup vs baseline: 1.0077x; 1.0077x over previous
#include <cuda_runtime.h>

// Problem constants (fixed by the reference):
//   input : (32, 1, 1024, 1024) float32
//   x_A, y_A, x_B, y_B, ordinal : (32, 100000) int32
//   output: scalar float32 = mean loss over 3.2M points
#define BB    32
#define HH    1024
#define WW    1024
#define NPTS  100000
#define TOTAL (BB * NPTS)      // 3,200,000
#define PPT   4                // points per thread
#define NTHREADS (TOTAL / PPT) // 800,000
#define TPB   256
#define NBLOCKS (NTHREADS / TPB) // 3125, exact

__device__ double       g_acc   = 0.0;
__device__ unsigned int g_count = 0;

__global__ __launch_bounds__(TPB) void loss_kernel(
    const float* __restrict__ depth,
    const int*   __restrict__ xA,
    const int*   __restrict__ yA,
    const int*   __restrict__ xB,
    const int*   __restrict__ yB,
    const int*   __restrict__ ordv,
    float*       __restrict__ out)
{
    const int t  = blockIdx.x * TPB + threadIdx.x;  // 0 .. 799999
    const int i0 = t * PPT;
    // NPTS % 4 == 0 -> all 4 points share one batch
    const int b  = i0 / NPTS;
    const float* __restrict__ img = depth + (size_t)b * (HH * WW);

    // Vectorized, coalesced index loads (16B each)
    const int4 ax = ((const int4*)xA)[t];
    const int4 ay = ((const int4*)yA)[t];
    const int4 bx = ((const int4*)xB)[t];
    const int4 by = ((const int4*)yB)[t];
    const int4 ov = ((const int4*)ordv)[t];

    int axv[PPT] = {ax.x, ax.y, ax.z, ax.w};
    int ayv[PPT] = {ay.x, ay.y, ay.z, ay.w};
    int bxv[PPT] = {bx.x, bx.y, bx.z, bx.w};
    int byv[PPT] = {by.x, by.y, by.z, by.w};
    int ovv[PPT] = {ov.x, ov.y, ov.z, ov.w};

    // Issue all 8 gathers first (max MLP), then compute
    float zA[PPT], zB[PPT];
    #pragma unroll
    for (int k = 0; k < PPT; k++) {
        zA[k] = __ldg(&img[ayv[k] * WW + axv[k]]);
        zB[k] = __ldg(&img[byv[k] * WW + bxv[k]]);
    }

    float l = 0.0f;
    #pragma unroll
    for (int k = 0; k < PPT; k++) {
        float diff = zA[k] - zB[k];
        float gt   = (float)(ovv[k] - 1);        // -1, 0, +1
        float mask = fabsf(gt);                  // 0 or 1
        // stable softplus(-gt*diff); when gt==0 this is ln2 but mask kills it
        float x  = -gt * diff;
        float sp = fmaxf(x, 0.0f) + log1pf(expf(-fabsf(x)));
        l += mask * sp + (1.0f - mask) * diff * diff;
    }

    // Warp reduction
    #pragma unroll
    for (int off = 16; off > 0; off >>= 1)
        l += __shfl_down_sync(0xffffffffu, l, off);

    __shared__ float warpsums[TPB / 32];
    const int lane = threadIdx.x & 31;
    const int wid  = threadIdx.x >> 5;
    if (lane == 0) warpsums[wid] = l;
    __syncthreads();

    __shared__ bool isLast;
    if (wid == 0) {
        float s = (lane < (TPB / 32)) ? warpsums[lane] : 0.0f;
        #pragma unroll
        for (int off = 4; off > 0; off >>= 1)
            s += __shfl_down_sync(0xffffffffu, s, off);
        if (lane == 0) {
            atomicAdd(&g_acc, (double)s);
            __threadfence();
            unsigned int old = atomicAdd(&g_count, 1u);
            isLast = (old == (unsigned int)(gridDim.x - 1));
        }
    }
    __syncthreads();

    // Last block finalizes and resets state for the next graph replay
    if (isLast && threadIdx.x == 0) {
        __threadfence();
        double acc = *((volatile double*)&g_acc);
        *out = (float)(acc / (double)TOTAL);
        *((volatile double*)&g_acc) = 0.0;
        __threadfence();
        *((volatile unsigned int*)&g_count) = 0u;
    }
}

extern "C" void kernel_launch(void* const* d_in, const int* in_sizes, int n_in,
                              void* d_out, int out_size)
{
    const float* depth = (const float*)d_in[0];
    const int*   xA    = (const int*)d_in[1];
    const int*   yA    = (const int*)d_in[2];
    const int*   xB    = (const int*)d_in[3];
    const int*   yB    = (const int*)d_in[4];
    const int*   ordv  = (const int*)d_in[5];
    float*       out   = (float*)d_out;

    loss_kernel<<<NBLOCKS, TPB>>>(depth, xA, yA, xB, yB, ordv, out);
}

// round 4
// speedup vs baseline: 1.0119x; 1.0042x over previous
#include <cuda_runtime.h>

// Problem constants (fixed by the reference):
//   input : (32, 1, 1024, 1024) float32
//   x_A, y_A, x_B, y_B, ordinal : (32, 100000) int32
//   output: scalar float32 = mean loss over 3.2M points
#define BB    32
#define HH    1024
#define WW    1024
#define NPTS  100000
#define TOTAL (BB * NPTS)        // 3,200,000
#define PPT   8                  // points per thread (NPTS % 8 == 0)
#define NTHREADS (TOTAL / PPT)   // 400,000
#define TPB   256
#define NBLOCKS ((NTHREADS + TPB - 1) / TPB)  // 1563 (last block partial)

__device__ double       g_acc   = 0.0;
__device__ unsigned int g_count = 0;

__global__ __launch_bounds__(TPB) void loss_kernel(
    const float* __restrict__ depth,
    const int*   __restrict__ xA,
    const int*   __restrict__ yA,
    const int*   __restrict__ xB,
    const int*   __restrict__ yB,
    const int*   __restrict__ ordv,
    float*       __restrict__ out)
{
    const int t = blockIdx.x * TPB + threadIdx.x;   // 0 .. 400127

    float l = 0.0f;
    if (t < NTHREADS) {
        // NPTS % 8 == 0 -> all 8 points of this thread share one batch
        const int b = t / (NPTS / PPT);             // t / 12500
        const float* __restrict__ img = depth + (size_t)b * (HH * WW);

        // Streaming (evict-first) vectorized index loads: these 64 MB are
        // touched exactly once — keep them from displacing depth in L2.
        const int4* xA4 = (const int4*)xA;
        const int4* yA4 = (const int4*)yA;
        const int4* xB4 = (const int4*)xB;
        const int4* yB4 = (const int4*)yB;
        const int4* ov4 = (const int4*)ordv;

        int4 ax0 = __ldcs(xA4 + 2 * t);
        int4 ax1 = __ldcs(xA4 + 2 * t + 1);
        int4 ay0 = __ldcs(yA4 + 2 * t);
        int4 ay1 = __ldcs(yA4 + 2 * t + 1);
        int4 bx0 = __ldcs(xB4 + 2 * t);
        int4 bx1 = __ldcs(xB4 + 2 * t + 1);
        int4 by0 = __ldcs(yB4 + 2 * t);
        int4 by1 = __ldcs(yB4 + 2 * t + 1);
        int4 ov0 = __ldcs(ov4 + 2 * t);
        int4 ov1 = __ldcs(ov4 + 2 * t + 1);

        int axv[PPT] = {ax0.x, ax0.y, ax0.z, ax0.w, ax1.x, ax1.y, ax1.z, ax1.w};
        int ayv[PPT] = {ay0.x, ay0.y, ay0.z, ay0.w, ay1.x, ay1.y, ay1.z, ay1.w};
        int bxv[PPT] = {bx0.x, bx0.y, bx0.z, bx0.w, bx1.x, bx1.y, bx1.z, bx1.w};
        int byv[PPT] = {by0.x, by0.y, by0.z, by0.w, by1.x, by1.y, by1.z, by1.w};
        int ovv[PPT] = {ov0.x, ov0.y, ov0.z, ov0.w, ov1.x, ov1.y, ov1.z, ov1.w};

        // Issue all 16 gathers back-to-back (max MLP), then compute
        float zA[PPT], zB[PPT];
        #pragma unroll
        for (int k = 0; k < PPT; k++) {
            zA[k] = __ldg(&img[ayv[k] * WW + axv[k]]);
            zB[k] = __ldg(&img[byv[k] * WW + bxv[k]]);
        }

        #pragma unroll
        for (int k = 0; k < PPT; k++) {
            float diff = zA[k] - zB[k];
            float gt   = (float)(ovv[k] - 1);        // -1, 0, +1
            float mask = fabsf(gt);                  // 0 or 1
            float x    = -gt * diff;
            float sp   = fmaxf(x, 0.0f) + log1pf(expf(-fabsf(x)));
            l += mask * sp + (1.0f - mask) * diff * diff;
        }
    }

    // Warp reduction
    #pragma unroll
    for (int off = 16; off > 0; off >>= 1)
        l += __shfl_down_sync(0xffffffffu, l, off);

    __shared__ float warpsums[TPB / 32];
    const int lane = threadIdx.x & 31;
    const int wid  = threadIdx.x >> 5;
    if (lane == 0) warpsums[wid] = l;
    __syncthreads();

    __shared__ bool isLast;
    if (wid == 0) {
        float s = (lane < (TPB / 32)) ? warpsums[lane] : 0.0f;
        #pragma unroll
        for (int off = 4; off > 0; off >>= 1)
            s += __shfl_down_sync(0xffffffffu, s, off);
        if (lane == 0) {
            atomicAdd(&g_acc, (double)s);
            __threadfence();
            unsigned int old = atomicAdd(&g_count, 1u);
            isLast = (old == (unsigned int)(gridDim.x - 1));
        }
    }
    __syncthreads();

    // Last block finalizes and resets state for the next graph replay
    if (isLast && threadIdx.x == 0) {
        __threadfence();
        double acc = *((volatile double*)&g_acc);
        *out = (float)(acc / (double)TOTAL);
        *((volatile double*)&g_acc) = 0.0;
        __threadfence();
        *((volatile unsigned int*)&g_count) = 0u;
    }
}

extern "C" void kernel_launch(void* const* d_in, const int* in_sizes, int n_in,
                              void* d_out, int out_size)
{
    const float* depth = (const float*)d_in[0];
    const int*   xA    = (const int*)d_in[1];
    const int*   yA    = (const int*)d_in[2];
    const int*   xB    = (const int*)d_in[3];
    const int*   yB    = (const int*)d_in[4];
    const int*   ordv  = (const int*)d_in[5];
    float*       out   = (float*)d_out;

    loss_kernel<<<NBLOCKS, TPB>>>(depth, xA, yA, xB, yB, ordv, out);
}